// round 4
// baseline (speedup 1.0000x reference)
#include <cuda_runtime.h>
#include <cstddef>

// ---------------------------------------------------------------------------
// ReactionCenterPredictor
//   inputs (metadata order):
//     0: atom_embeddings  [N,32]  f32
//     1: bond_energies    [E,1]   f32
//     2: W_e [1,1] f32   3: b_e [1] f32
//     4: W1  [16,33] f32 5: b1 [16] f32
//     6: W2  [1,16]  f32 7: b2 [1] f32
//     8: edge_index [2,E] int64 (or int32 if jax x64 disabled — sniffed)
//   output: [E/2] f32
//
// Strategy:
//   K1: per-atom projection p[n][k] = atom[n]·W1[k,:32] + 0.5*b1[k]  (64MB table)
//   K2: quad-cooperative edge kernel: 4 lanes per 64B row gather,
//       shuffle-sum endpoints, shuffle-reduce dot, shuffle pair-average.
// ---------------------------------------------------------------------------

#define MAX_N 1000000

__device__ __align__(16) float4 g_proj[MAX_N * 4];  // 64 MB scratch (static: allowed)
__device__ int g_idx32;                             // 1 if edge_index is int32

struct CParams {
    float W1[16 * 33];  // row-major [16][33]; col 32 is the energy weight
    float b1[16];
    float W2[16];
    float b2;
    float We;   // W_e[0][0]
    float be0;  // b_e[0]
};
__constant__ CParams cp;

// ---------------------------------------------------------------------------
// Sniff edge_index element width. int64 values are < 2^20, so every odd u32
// word (high half) is 0. int32 data has real indices at odd positions.
// ---------------------------------------------------------------------------
__global__ void sniff_kernel(const unsigned int* __restrict__ ei_u32) {
    if (threadIdx.x == 0) {
        unsigned int acc = 0;
#pragma unroll
        for (int i = 1; i < 128; i += 2) acc |= ei_u32[i];
        g_idx32 = (acc != 0) ? 1 : 0;
    }
}

// ---------------------------------------------------------------------------
// K1: per-atom 32->16 projection, b1/2 folded in.
// ---------------------------------------------------------------------------
__global__ void proj_kernel(const float* __restrict__ atoms, int n) {
    int i = blockIdx.x * blockDim.x + threadIdx.x;
    if (i >= n) return;

    const float4* __restrict__ ar = reinterpret_cast<const float4*>(atoms) + (size_t)i * 8;
    float a[32];
#pragma unroll
    for (int q = 0; q < 8; q++) {
        float4 v = __ldg(ar + q);
        a[4 * q + 0] = v.x; a[4 * q + 1] = v.y;
        a[4 * q + 2] = v.z; a[4 * q + 3] = v.w;
    }

    float acc[16];
#pragma unroll
    for (int k = 0; k < 16; k++) acc[k] = 0.5f * cp.b1[k];

#pragma unroll
    for (int j = 0; j < 32; j++) {
        float aj = a[j];
#pragma unroll
        for (int k = 0; k < 16; k++)
            acc[k] = fmaf(aj, cp.W1[k * 33 + j], acc[k]);
    }

#pragma unroll
    for (int c = 0; c < 4; c++)
        g_proj[(size_t)i * 4 + c] =
            make_float4(acc[4 * c + 0], acc[4 * c + 1], acc[4 * c + 2], acc[4 * c + 3]);
}

// ---------------------------------------------------------------------------
// K2: one warp handles 2 output pairs (= 4 edges = 8 gathered rows).
// Lane l: sub = l&3 (which float4 of the row), q = l>>2 (which row).
//   q layout: [pair p = q>>2][edge sel = q&2 ? i+H : i][endpoint = q&1 ? dst : src]
// psum   : shfl_xor 4  (src+dst)
// dot    : shfl_xor 1,2 (16-wide dot over 4 lanes x 4 elems)
// pairavg: shfl_xor 8  (score_i + score_{i+H})
// ---------------------------------------------------------------------------
__global__ void edge_kernel(const float* __restrict__ be,
                            const void* __restrict__ ei_raw,
                            float* __restrict__ out,
                            int E, int H) {
    int gtid = blockIdx.x * blockDim.x + threadIdx.x;
    int w = gtid >> 5;
    int l = gtid & 31;
    int base = w * 2;
    if (base >= H) return;  // warp-uniform exit

    int sub = l & 3;
    int q = l >> 2;

    int o = base + (q >> 2);
    if (o >= H) o = H - 1;  // clamp; redundant-safe (only hits if H odd)
    int e = o + ((q & 2) ? H : 0);
    int off = e + ((q & 1) ? E : 0);

    int r;
    if (g_idx32) {
        r = __ldg(reinterpret_cast<const int*>(ei_raw) + off);
    } else {
        r = (int)__ldg(reinterpret_cast<const long long*>(ei_raw) + off);
    }

    float4 v = __ldg(&g_proj[(size_t)r * 4 + sub]);

    // endpoint sum (partner lane l^4 holds the other endpoint, same sub)
    const unsigned FULL = 0xffffffffu;
    float s0 = v.x + __shfl_xor_sync(FULL, v.x, 4);
    float s1 = v.y + __shfl_xor_sync(FULL, v.y, 4);
    float s2 = v.z + __shfl_xor_sync(FULL, v.z, 4);
    float s3 = v.w + __shfl_xor_sync(FULL, v.w, 4);

    // energy feature for this edge
    float ef = fmaf(__ldg(be + e), cp.We, cp.be0);

    int k0 = sub * 4;
    float h0 = fmaxf(fmaf(ef, cp.W1[(k0 + 0) * 33 + 32], s0), 0.0f);
    float h1 = fmaxf(fmaf(ef, cp.W1[(k0 + 1) * 33 + 32], s1), 0.0f);
    float h2 = fmaxf(fmaf(ef, cp.W1[(k0 + 2) * 33 + 32], s2), 0.0f);
    float h3 = fmaxf(fmaf(ef, cp.W1[(k0 + 3) * 33 + 32], s3), 0.0f);

    float lg = h0 * cp.W2[k0 + 0];
    lg = fmaf(h1, cp.W2[k0 + 1], lg);
    lg = fmaf(h2, cp.W2[k0 + 2], lg);
    lg = fmaf(h3, cp.W2[k0 + 3], lg);

    // reduce 16-dot across the quad
    lg += __shfl_xor_sync(FULL, lg, 1);
    lg += __shfl_xor_sync(FULL, lg, 2);

    lg += cp.b2;
    float sc = 1.0f / (1.0f + __expf(-lg));

    // average the two paired edges (partner lane l^8 flips q&2)
    float res = 0.5f * (sc + __shfl_xor_sync(FULL, sc, 8));

    if ((l & 15) == 0 && o < H) out[o] = res;
}

// ---------------------------------------------------------------------------

extern "C" void kernel_launch(void* const* d_in, const int* in_sizes, int n_in,
                              void* d_out, int out_size) {
    const float* atoms = (const float*)d_in[0];
    const float* be    = (const float*)d_in[1];
    const void*  ei    = d_in[8];
    float* out = (float*)d_out;

    int n = in_sizes[0] / 32;  // atoms
    int E = in_sizes[1];       // edges (bond_energies is [E,1])
    int H = out_size;          // E/2

    // Stage tiny learned params into constant memory (graph-capturable D2D copies).
    cudaMemcpyToSymbolAsync(cp, d_in[4], 528 * sizeof(float), offsetof(CParams, W1),
                            cudaMemcpyDeviceToDevice, 0);
    cudaMemcpyToSymbolAsync(cp, d_in[5], 16 * sizeof(float), offsetof(CParams, b1),
                            cudaMemcpyDeviceToDevice, 0);
    cudaMemcpyToSymbolAsync(cp, d_in[6], 16 * sizeof(float), offsetof(CParams, W2),
                            cudaMemcpyDeviceToDevice, 0);
    cudaMemcpyToSymbolAsync(cp, d_in[7], sizeof(float), offsetof(CParams, b2),
                            cudaMemcpyDeviceToDevice, 0);
    cudaMemcpyToSymbolAsync(cp, d_in[2], sizeof(float), offsetof(CParams, We),
                            cudaMemcpyDeviceToDevice, 0);
    cudaMemcpyToSymbolAsync(cp, d_in[3], sizeof(float), offsetof(CParams, be0),
                            cudaMemcpyDeviceToDevice, 0);

    sniff_kernel<<<1, 32>>>((const unsigned int*)ei);

    proj_kernel<<<(n + 255) / 256, 256>>>(atoms, n);

    long long warps = (H + 1) / 2;           // 2 outputs per warp
    long long threads = warps * 32;
    int blocks = (int)((threads + 255) / 256);
    edge_kernel<<<blocks, 256>>>(be, ei, out, E, H);
}

// round 5
// speedup vs baseline: 1.8568x; 1.8568x over previous
#include <cuda_runtime.h>
#include <cuda_fp16.h>
#include <cstddef>

// ---------------------------------------------------------------------------
// ReactionCenterPredictor
//   inputs (metadata order):
//     0: atom_embeddings  [N,32]  f32
//     1: bond_energies    [E,1]   f32
//     2: W_e [1,1] f32   3: b_e [1] f32
//     4: W1  [16,33] f32 5: b1 [16] f32
//     6: W2  [1,16]  f32 7: b2 [1] f32
//     8: edge_index [2,E] int64 (or int32 — sniffed at runtime)
//   output: [E/2] f32
//
// v2: no constant memory (Blackwell LDC floor=8 made it the bottleneck),
//     fp16 projection table (32 MB, L2-resident; gather traffic halved),
//     4 outputs per warp, 2 kernel graph nodes total.
// ---------------------------------------------------------------------------

#define MAX_N 1000000

__device__ __align__(16) __half g_projh[MAX_N * 16];  // 32 MB fp16 projections
__device__ __align__(16) float2 g_wpack[16];          // {W1[k][32], W2[k]}
__device__ __align__(16) float4 g_scal;               // {We, be0, b2, 0}
__device__ int g_idx32;                               // 1 if edge_index is int32

__device__ __forceinline__ unsigned f2_to_h2u(float a, float b) {
    __half2 h = __floats2half2_rn(a, b);
    return *reinterpret_cast<unsigned*>(&h);
}
__device__ __forceinline__ float2 h2u_to_f2(unsigned u) {
    return __half22float2(*reinterpret_cast<__half2*>(&u));
}

// ---------------------------------------------------------------------------
// K1: per-atom 32->16 projection (b1/2 folded), weights in SHARED not constant.
// Block 0 additionally: packs edge-kernel weights and sniffs index dtype.
// ---------------------------------------------------------------------------
__global__ void proj_kernel(const float* __restrict__ atoms,
                            const float* __restrict__ W1,   // [16,33]
                            const float* __restrict__ b1,   // [16]
                            const float* __restrict__ W2,   // [16]
                            const float* __restrict__ b2,   // [1]
                            const float* __restrict__ We,   // [1]
                            const float* __restrict__ bE,   // [1]
                            const unsigned int* __restrict__ ei_u32,
                            int n) {
    __shared__ __align__(16) float sW1t[33 * 16];  // [j][k] transposed
    __shared__ float sb1[16];

    int tid = threadIdx.x;

    // One-time setup from block 0 (visible to edge_kernel via stream order).
    if (blockIdx.x == 0) {
        if (tid < 16)
            g_wpack[tid] = make_float2(__ldg(W1 + tid * 33 + 32), __ldg(W2 + tid));
        if (tid == 0) {
            g_scal = make_float4(__ldg(We), __ldg(bE), __ldg(b2), 0.0f);
            unsigned int acc = 0;
#pragma unroll
            for (int i = 1; i < 128; i += 2) acc |= __ldg(ei_u32 + i);
            g_idx32 = (acc != 0) ? 1 : 0;
        }
    }

    // Stage transposed W1 + b1 into shared.
    for (int idx = tid; idx < 33 * 16; idx += blockDim.x) {
        int j = idx >> 4, k = idx & 15;
        sW1t[idx] = __ldg(W1 + k * 33 + j);
    }
    if (tid < 16) sb1[tid] = __ldg(b1 + tid);
    __syncthreads();

    int i = blockIdx.x * blockDim.x + tid;
    if (i >= n) return;

    const float4* __restrict__ ar = reinterpret_cast<const float4*>(atoms) + (size_t)i * 8;
    float a[32];
#pragma unroll
    for (int q = 0; q < 8; q++) {
        float4 v = __ldg(ar + q);
        a[4 * q + 0] = v.x; a[4 * q + 1] = v.y;
        a[4 * q + 2] = v.z; a[4 * q + 3] = v.w;
    }

    float acc[16];
#pragma unroll
    for (int k = 0; k < 16; k++) acc[k] = 0.5f * sb1[k];

#pragma unroll
    for (int j = 0; j < 32; j++) {
        float aj = a[j];
        const float4* wr = reinterpret_cast<const float4*>(&sW1t[j * 16]);
#pragma unroll
        for (int c = 0; c < 4; c++) {
            float4 w = wr[c];
            acc[4 * c + 0] = fmaf(aj, w.x, acc[4 * c + 0]);
            acc[4 * c + 1] = fmaf(aj, w.y, acc[4 * c + 1]);
            acc[4 * c + 2] = fmaf(aj, w.z, acc[4 * c + 2]);
            acc[4 * c + 3] = fmaf(aj, w.w, acc[4 * c + 3]);
        }
    }

    // Pack to fp16: 16 halves = 2 uint4.
    uint4 o0, o1;
    o0.x = f2_to_h2u(acc[0],  acc[1]);  o0.y = f2_to_h2u(acc[2],  acc[3]);
    o0.z = f2_to_h2u(acc[4],  acc[5]);  o0.w = f2_to_h2u(acc[6],  acc[7]);
    o1.x = f2_to_h2u(acc[8],  acc[9]);  o1.y = f2_to_h2u(acc[10], acc[11]);
    o1.z = f2_to_h2u(acc[12], acc[13]); o1.w = f2_to_h2u(acc[14], acc[15]);
    uint4* dst = reinterpret_cast<uint4*>(g_projh) + (size_t)i * 2;
    dst[0] = o0;
    dst[1] = o1;
}

// ---------------------------------------------------------------------------
// K2: 4 outputs per warp. Lane l: sub = l&1 (which 8-half chunk of the row),
// q = l>>1 (row 0..15). Row bits: endpoint=q&1, edgesel=q&2, pair=q>>2.
//   endpoint sum : shfl_xor 2   (raw uints, then add in fp32)
//   dot halves   : shfl_xor 1
//   pair average : shfl_xor 4
// ---------------------------------------------------------------------------
__global__ void edge_kernel(const float* __restrict__ be,
                            const void* __restrict__ ei_raw,
                            float* __restrict__ out,
                            int E, int H) {
    int gtid = blockIdx.x * blockDim.x + threadIdx.x;
    int w = gtid >> 5;
    int l = gtid & 31;
    int base = w * 4;
    if (base >= H) return;  // warp-uniform

    int sub = l & 1;
    int q = l >> 1;

    int o_raw = base + (q >> 2);
    int o = min(o_raw, H - 1);             // clamp for partial last warp
    int e = o + ((q & 2) ? H : 0);
    long long off = (long long)e + ((q & 1) ? (long long)E : 0);

    int r;
    if (g_idx32) {
        r = __ldg(reinterpret_cast<const int*>(ei_raw) + off);
    } else {
        r = (int)__ldg(reinterpret_cast<const long long*>(ei_raw) + off);
    }

    // Gather 16B (8 halves) of the 32B projection row.
    uint4 v = __ldg(reinterpret_cast<const uint4*>(g_projh) + (size_t)r * 2 + sub);

    const unsigned FULL = 0xffffffffu;
    unsigned px = __shfl_xor_sync(FULL, v.x, 2);
    unsigned py = __shfl_xor_sync(FULL, v.y, 2);
    unsigned pz = __shfl_xor_sync(FULL, v.z, 2);
    unsigned pw = __shfl_xor_sync(FULL, v.w, 2);

    float s[8];
    {
        float2 a, b;
        a = h2u_to_f2(v.x); b = h2u_to_f2(px); s[0] = a.x + b.x; s[1] = a.y + b.y;
        a = h2u_to_f2(v.y); b = h2u_to_f2(py); s[2] = a.x + b.x; s[3] = a.y + b.y;
        a = h2u_to_f2(v.z); b = h2u_to_f2(pz); s[4] = a.x + b.x; s[5] = a.y + b.y;
        a = h2u_to_f2(v.w); b = h2u_to_f2(pw); s[6] = a.x + b.x; s[7] = a.y + b.y;
    }

    float4 sc4 = g_scal;                                  // {We, be0, b2, 0}
    float ef = fmaf(__ldg(be + e), sc4.x, sc4.y);

    // Weights for k = sub*8 .. sub*8+7 : 4 x float4 = 8 x float2 {W1e, W2}.
    const float4* wp = reinterpret_cast<const float4*>(g_wpack) + sub * 4;
    float lg = 0.0f;
#pragma unroll
    for (int t = 0; t < 4; t++) {
        float4 wv = __ldg(wp + t);
        float h0 = fmaxf(fmaf(ef, wv.x, s[2 * t + 0]), 0.0f);
        float h1 = fmaxf(fmaf(ef, wv.z, s[2 * t + 1]), 0.0f);
        lg = fmaf(h0, wv.y, lg);
        lg = fmaf(h1, wv.w, lg);
    }

    lg += __shfl_xor_sync(FULL, lg, 1);   // combine the two half-rows
    lg += sc4.z;                          // + b2
    float sc = 1.0f / (1.0f + __expf(-lg));

    float res = 0.5f * (sc + __shfl_xor_sync(FULL, sc, 4));  // pair (i, i+H)

    if ((l & 7) == 0 && o_raw < H) out[o_raw] = res;
}

// ---------------------------------------------------------------------------

extern "C" void kernel_launch(void* const* d_in, const int* in_sizes, int n_in,
                              void* d_out, int out_size) {
    const float* atoms = (const float*)d_in[0];
    const float* be    = (const float*)d_in[1];
    const float* We    = (const float*)d_in[2];
    const float* bE    = (const float*)d_in[3];
    const float* W1    = (const float*)d_in[4];
    const float* b1    = (const float*)d_in[5];
    const float* W2    = (const float*)d_in[6];
    const float* b2    = (const float*)d_in[7];
    const void*  ei    = d_in[8];
    float* out = (float*)d_out;

    int n = in_sizes[0] / 32;  // atoms
    int E = in_sizes[1];       // edges
    int H = out_size;          // E/2

    proj_kernel<<<(n + 255) / 256, 256>>>(atoms, W1, b1, W2, b2, We, bE,
                                          (const unsigned int*)ei, n);

    long long warps = (H + 3) / 4;  // 4 outputs per warp
    long long threads = warps * 32;
    int blocks = (int)((threads + 255) / 256);
    edge_kernel<<<blocks, 256>>>(be, ei, out, E, H);
}

// round 7
// speedup vs baseline: 1.9409x; 1.0453x over previous
#include <cuda_runtime.h>
#include <cuda_fp16.h>

// ---------------------------------------------------------------------------
// ReactionCenterPredictor
//   inputs: 0 atoms[N,32] f32 | 1 bond_energies[E,1] f32 | 2 W_e[1,1] | 3 b_e[1]
//           4 W1[16,33] | 5 b1[16] | 6 W2[1,16] | 7 b2[1] | 8 edge_index[2,E] i64/i32
//   output: [E/2] f32
//
// v3: proj uses packed fma.rn.f32x2 (halves FMA issue); edge stages weights in
//     shared (kills per-thread L1tex weight LDGs) and does 8 outputs/warp with
//     both gathers in flight.
// ---------------------------------------------------------------------------

#define MAX_N 1000000

__device__ __align__(16) __half g_projh[MAX_N * 16];  // 32 MB fp16 projection table
__device__ int g_idx32;                               // 1 if edge_index is int32

// ---- packed f32x2 helpers (sm_100a) ---------------------------------------
__device__ __forceinline__ unsigned long long pack2(float x, float y) {
    unsigned long long r;
    asm("mov.b64 %0, {%1, %2};" : "=l"(r) : "f"(x), "f"(y));
    return r;
}
__device__ __forceinline__ void unpack2(unsigned long long v, float& x, float& y) {
    asm("mov.b64 {%0, %1}, %2;" : "=f"(x), "=f"(y) : "l"(v));
}
__device__ __forceinline__ unsigned long long ffma2(unsigned long long a,
                                                    unsigned long long b,
                                                    unsigned long long c) {
    unsigned long long d;
    asm("fma.rn.f32x2 %0, %1, %2, %3;" : "=l"(d) : "l"(a), "l"(b), "l"(c));
    return d;
}
__device__ __forceinline__ float2 h2u_to_f2(unsigned u) {
    return __half22float2(*reinterpret_cast<__half2*>(&u));
}

// ---------------------------------------------------------------------------
// K1: per-atom 32->16 projection, b1/2 folded, packed-FFMA2 mainloop.
// Block 0 also sniffs the edge_index dtype.
// ---------------------------------------------------------------------------
__global__ void proj_kernel(const float* __restrict__ atoms,
                            const float* __restrict__ W1,   // [16,33]
                            const float* __restrict__ b1,   // [16]
                            const unsigned int* __restrict__ ei_u32,
                            int n) {
    __shared__ __align__(16) float sW[33 * 16];  // [j][k] transposed
    __shared__ float sb1[16];

    int tid = threadIdx.x;

    if (blockIdx.x == 0 && tid == 0) {
        unsigned int acc = 0;
#pragma unroll
        for (int i = 1; i < 128; i += 2) acc |= __ldg(ei_u32 + i);
        g_idx32 = (acc != 0) ? 1 : 0;
    }

    for (int idx = tid; idx < 33 * 16; idx += blockDim.x) {
        int j = idx >> 4, k = idx & 15;
        sW[idx] = __ldg(W1 + k * 33 + j);
    }
    if (tid < 16) sb1[tid] = __ldg(b1 + tid);
    __syncthreads();

    int i = blockIdx.x * blockDim.x + tid;
    if (i >= n) return;

    const float4* __restrict__ ar = reinterpret_cast<const float4*>(atoms) + (size_t)i * 8;
    float a[32];
#pragma unroll
    for (int q = 0; q < 8; q++) {
        float4 v = __ldg(ar + q);
        a[4 * q + 0] = v.x; a[4 * q + 1] = v.y;
        a[4 * q + 2] = v.z; a[4 * q + 3] = v.w;
    }

    unsigned long long acc[8];
#pragma unroll
    for (int c = 0; c < 8; c++)
        acc[c] = pack2(0.5f * sb1[2 * c], 0.5f * sb1[2 * c + 1]);

#pragma unroll
    for (int j = 0; j < 32; j++) {
        unsigned long long aj2 = pack2(a[j], a[j]);
        const ulonglong2* wr = reinterpret_cast<const ulonglong2*>(&sW[j * 16]);
#pragma unroll
        for (int c = 0; c < 4; c++) {
            ulonglong2 w = wr[c];
            acc[2 * c + 0] = ffma2(aj2, w.x, acc[2 * c + 0]);
            acc[2 * c + 1] = ffma2(aj2, w.y, acc[2 * c + 1]);
        }
    }

    // Unpack -> fp16 pairs -> two 16B stores.
    uint4 o0, o1;
    float x, y;
    unsigned u[8];
#pragma unroll
    for (int c = 0; c < 8; c++) {
        unpack2(acc[c], x, y);
        __half2 h = __floats2half2_rn(x, y);
        u[c] = *reinterpret_cast<unsigned*>(&h);
    }
    o0 = make_uint4(u[0], u[1], u[2], u[3]);
    o1 = make_uint4(u[4], u[5], u[6], u[7]);
    uint4* dst = reinterpret_cast<uint4*>(g_projh) + (size_t)i * 2;
    dst[0] = o0;
    dst[1] = o1;
}

// ---------------------------------------------------------------------------
// K2: 8 outputs per warp = 2 groups of 4. Lane l: sub=l&1 (row half),
// endpoint=(l>>1)&1, edgesel=(l>>2)&1, dq=l>>3 (output within group).
//   endpoint sum : shfl_xor 2
//   dot halves   : shfl_xor 1
//   pair average : shfl_xor 4
// Both groups' index+gather loads issued before any dependent math.
// ---------------------------------------------------------------------------
struct EdgeW { float4 wv[4]; };  // 8 x {W1_energy, W2} pairs for this sub

__device__ __forceinline__ float edge_score(uint4 v, float ef, const EdgeW& W, float b2v) {
    const unsigned FULL = 0xffffffffu;
    unsigned px = __shfl_xor_sync(FULL, v.x, 2);
    unsigned py = __shfl_xor_sync(FULL, v.y, 2);
    unsigned pz = __shfl_xor_sync(FULL, v.z, 2);
    unsigned pw = __shfl_xor_sync(FULL, v.w, 2);

    float s[8];
    float2 a, b;
    a = h2u_to_f2(v.x); b = h2u_to_f2(px); s[0] = a.x + b.x; s[1] = a.y + b.y;
    a = h2u_to_f2(v.y); b = h2u_to_f2(py); s[2] = a.x + b.x; s[3] = a.y + b.y;
    a = h2u_to_f2(v.z); b = h2u_to_f2(pz); s[4] = a.x + b.x; s[5] = a.y + b.y;
    a = h2u_to_f2(v.w); b = h2u_to_f2(pw); s[6] = a.x + b.x; s[7] = a.y + b.y;

    float lg = 0.0f;
#pragma unroll
    for (int t = 0; t < 4; t++) {
        float4 wv = W.wv[t];
        float h0 = fmaxf(fmaf(ef, wv.x, s[2 * t + 0]), 0.0f);
        float h1 = fmaxf(fmaf(ef, wv.z, s[2 * t + 1]), 0.0f);
        lg = fmaf(h0, wv.y, lg);
        lg = fmaf(h1, wv.w, lg);
    }
    lg += __shfl_xor_sync(FULL, lg, 1);
    lg += b2v;
    return 1.0f / (1.0f + __expf(-lg));
}

__global__ void edge_kernel(const float* __restrict__ be,
                            const void* __restrict__ ei_raw,
                            const float* __restrict__ W1,
                            const float* __restrict__ W2,
                            const float* __restrict__ We,
                            const float* __restrict__ bE,
                            const float* __restrict__ b2,
                            float* __restrict__ out,
                            int E, int H) {
    __shared__ __align__(16) float2 swp[16];  // {W1[k][32], W2[k]}
    __shared__ float sWe, sbe0, sb2;
    __shared__ int sidx32;

    int tid = threadIdx.x;
    if (tid < 16) {
        swp[tid] = make_float2(__ldg(W1 + tid * 33 + 32), __ldg(W2 + tid));
    } else if (tid == 16) sWe = __ldg(We);
    else if (tid == 17) sbe0 = __ldg(bE);
    else if (tid == 18) sb2 = __ldg(b2);
    else if (tid == 19) sidx32 = g_idx32;
    __syncthreads();

    int gtid = blockIdx.x * blockDim.x + tid;
    int w = gtid >> 5;
    int l = gtid & 31;
    int base0 = w * 8;
    if (base0 >= H) return;  // warp-uniform

    int sub = l & 1;
    int dq = l >> 3;                 // output slot within group
    int eselH = ((l >> 2) & 1) ? H : 0;
    int epE = ((l >> 1) & 1) ? E : 0;

    // Weights for k = sub*8 .. sub*8+7 (LDS.128 x4, broadcast).
    EdgeW W;
    {
        const float4* wp = reinterpret_cast<const float4*>(swp) + sub * 4;
#pragma unroll
        for (int t = 0; t < 4; t++) W.wv[t] = wp[t];
    }
    float Wev = sWe, be0v = sbe0, b2v = sb2;
    int idx32 = sidx32;
    const unsigned FULL = 0xffffffffu;

    int o0r = base0 + dq;
    int o1r = base0 + 4 + dq;
    int o0 = min(o0r, H - 1);
    int o1 = min(o1r, H - 1);
    int e0 = o0 + eselH;
    int e1 = o1 + eselH;
    int off0 = e0 + epE;
    int off1 = e1 + epE;

    int r0, r1;
    if (idx32) {
        const int* p = reinterpret_cast<const int*>(ei_raw);
        r0 = __ldg(p + off0);
        r1 = __ldg(p + off1);
    } else {
        const long long* p = reinterpret_cast<const long long*>(ei_raw);
        r0 = (int)__ldg(p + off0);
        r1 = (int)__ldg(p + off1);
    }

    const uint4* tab = reinterpret_cast<const uint4*>(g_projh);
    uint4 v0 = __ldg(tab + (size_t)r0 * 2 + sub);
    uint4 v1 = __ldg(tab + (size_t)r1 * 2 + sub);
    float ef0 = fmaf(__ldg(be + e0), Wev, be0v);
    float ef1 = fmaf(__ldg(be + e1), Wev, be0v);

    float sc0 = edge_score(v0, ef0, W, b2v);
    float sc1 = edge_score(v1, ef1, W, b2v);

    float res0 = 0.5f * (sc0 + __shfl_xor_sync(FULL, sc0, 4));
    float res1 = 0.5f * (sc1 + __shfl_xor_sync(FULL, sc1, 4));

    if ((l & 7) == 0) {
        if (o0r < H) out[o0r] = res0;
        if (o1r < H) out[o1r] = res1;
    }
}

// ---------------------------------------------------------------------------

extern "C" void kernel_launch(void* const* d_in, const int* in_sizes, int n_in,
                              void* d_out, int out_size) {
    const float* atoms = (const float*)d_in[0];
    const float* be    = (const float*)d_in[1];
    const float* We    = (const float*)d_in[2];
    const float* bE    = (const float*)d_in[3];
    const float* W1    = (const float*)d_in[4];
    const float* b1    = (const float*)d_in[5];
    const float* W2    = (const float*)d_in[6];
    const float* b2    = (const float*)d_in[7];
    const void*  ei    = d_in[8];
    float* out = (float*)d_out;

    int n = in_sizes[0] / 32;  // atoms
    int E = in_sizes[1];       // edges
    int H = out_size;          // E/2

    proj_kernel<<<(n + 255) / 256, 256>>>(atoms, W1, b1, (const unsigned int*)ei, n);

    long long warps = ((long long)H + 7) / 8;  // 8 outputs per warp
    long long threads = warps * 32;
    int blocks = (int)((threads + 255) / 256);
    edge_kernel<<<blocks, 256>>>(be, ei, W1, W2, We, bE, b2, out, E, H);
}

// round 9
// speedup vs baseline: 2.1585x; 1.1121x over previous
#include <cuda_runtime.h>
#include <cuda_fp16.h>

// ---------------------------------------------------------------------------
// ReactionCenterPredictor
//   inputs: 0 atoms[N,32] f32 | 1 bond_energies[E,1] f32 | 2 W_e[1,1] | 3 b_e[1]
//           4 W1[16,33] | 5 b1[16] | 6 W2[1,16] | 7 b2[1] | 8 edge_index[2,E] i64/i32
//   output: [E/2] f32
//
// v4 (resubmit after infra failure): edge does 16 outputs/warp (4 groups,
//     front-batched loads, strength-reduced addressing) with HADD2 endpoint
//     sums (halves F2F converts); proj does 2 atoms/thread sharing weight LDS.
// ---------------------------------------------------------------------------

#define MAX_N 1000000

__device__ __align__(16) __half g_projh[MAX_N * 16];  // 32 MB fp16 projection table
__device__ int g_idx32;                               // 1 if edge_index is int32

// ---- packed f32x2 helpers (sm_100a) ---------------------------------------
__device__ __forceinline__ unsigned long long pack2(float x, float y) {
    unsigned long long r;
    asm("mov.b64 %0, {%1, %2};" : "=l"(r) : "f"(x), "f"(y));
    return r;
}
__device__ __forceinline__ void unpack2(unsigned long long v, float& x, float& y) {
    asm("mov.b64 {%0, %1}, %2;" : "=f"(x), "=f"(y) : "l"(v));
}
__device__ __forceinline__ unsigned long long ffma2(unsigned long long a,
                                                    unsigned long long b,
                                                    unsigned long long c) {
    unsigned long long d;
    asm("fma.rn.f32x2 %0, %1, %2, %3;" : "=l"(d) : "l"(a), "l"(b), "l"(c));
    return d;
}
__device__ __forceinline__ __half2 u2h(unsigned u) {
    return *reinterpret_cast<__half2*>(&u);
}

// ---------------------------------------------------------------------------
// K1: per-atom 32->16 projection, b1/2 folded. 2 atoms per thread (i, i+256)
// share every weight LDS.128. Block 0 also sniffs the edge_index dtype.
// ---------------------------------------------------------------------------
__global__ void proj_kernel(const float* __restrict__ atoms,
                            const float* __restrict__ W1,   // [16,33]
                            const float* __restrict__ b1,   // [16]
                            const unsigned int* __restrict__ ei_u32,
                            int n) {
    __shared__ __align__(16) float sW[32 * 16];  // [j][k] transposed (j<32 only)
    __shared__ float sb1[16];

    int tid = threadIdx.x;

    if (blockIdx.x == 0 && tid == 0) {
        unsigned int acc = 0;
#pragma unroll
        for (int i = 1; i < 128; i += 2) acc |= __ldg(ei_u32 + i);
        g_idx32 = (acc != 0) ? 1 : 0;
    }

    for (int idx = tid; idx < 32 * 16; idx += blockDim.x) {
        int j = idx >> 4, k = idx & 15;
        sW[idx] = __ldg(W1 + k * 33 + j);
    }
    if (tid < 16) sb1[tid] = __ldg(b1 + tid);
    __syncthreads();

    int i0 = blockIdx.x * 512 + tid;   // atom A
    int i1 = i0 + 256;                 // atom B (coalesced pairing)
    bool val0 = (i0 < n), val1 = (i1 < n);
    if (!val0) return;                 // if i0 oob, i1 is too

    const float4* __restrict__ a0 = reinterpret_cast<const float4*>(atoms) + (size_t)i0 * 8;
    const float4* __restrict__ a1 = reinterpret_cast<const float4*>(atoms) + (size_t)i1 * 8;

    unsigned long long acc0[8], acc1[8];
#pragma unroll
    for (int c = 0; c < 8; c++) {
        unsigned long long b = pack2(0.5f * sb1[2 * c], 0.5f * sb1[2 * c + 1]);
        acc0[c] = b;
        acc1[c] = b;
    }

#pragma unroll
    for (int jc = 0; jc < 8; jc++) {
        float4 A0 = __ldg(a0 + jc);
        float4 A1 = val1 ? __ldg(a1 + jc) : make_float4(0.f, 0.f, 0.f, 0.f);
        float av0[4] = {A0.x, A0.y, A0.z, A0.w};
        float av1[4] = {A1.x, A1.y, A1.z, A1.w};
#pragma unroll
        for (int jj = 0; jj < 4; jj++) {
            int j = 4 * jc + jj;
            unsigned long long aj0 = pack2(av0[jj], av0[jj]);
            unsigned long long aj1 = pack2(av1[jj], av1[jj]);
            const ulonglong2* wr = reinterpret_cast<const ulonglong2*>(&sW[j * 16]);
#pragma unroll
            for (int c = 0; c < 4; c++) {
                ulonglong2 w = wr[c];   // 4 weights (k = 4c .. 4c+3)
                acc0[2 * c + 0] = ffma2(aj0, w.x, acc0[2 * c + 0]);
                acc0[2 * c + 1] = ffma2(aj0, w.y, acc0[2 * c + 1]);
                acc1[2 * c + 0] = ffma2(aj1, w.x, acc1[2 * c + 0]);
                acc1[2 * c + 1] = ffma2(aj1, w.y, acc1[2 * c + 1]);
            }
        }
    }

    // Pack fp32 accumulators -> fp16 halves -> 16B stores.
    float x, y;
    unsigned u0[8], u1[8];
#pragma unroll
    for (int c = 0; c < 8; c++) {
        unpack2(acc0[c], x, y);
        __half2 h = __floats2half2_rn(x, y);
        u0[c] = *reinterpret_cast<unsigned*>(&h);
        unpack2(acc1[c], x, y);
        h = __floats2half2_rn(x, y);
        u1[c] = *reinterpret_cast<unsigned*>(&h);
    }
    uint4* dst0 = reinterpret_cast<uint4*>(g_projh) + (size_t)i0 * 2;
    dst0[0] = make_uint4(u0[0], u0[1], u0[2], u0[3]);
    dst0[1] = make_uint4(u0[4], u0[5], u0[6], u0[7]);
    if (val1) {
        uint4* dst1 = reinterpret_cast<uint4*>(g_projh) + (size_t)i1 * 2;
        dst1[0] = make_uint4(u1[0], u1[1], u1[2], u1[3]);
        dst1[1] = make_uint4(u1[4], u1[5], u1[6], u1[7]);
    }
}

// ---------------------------------------------------------------------------
// K2: 16 outputs per warp = 4 groups of 4. Lane l: sub=l&1 (row half),
// endpoint=(l>>1)&1, edgesel=(l>>2)&1, dq=l>>3 (output slot within group).
// Group g covers output base0 + 4*g + dq  ->  offsets advance by +4 per group.
//   endpoint sum : shfl_xor 2  (then HADD2 in half2)
//   dot halves   : shfl_xor 1
//   pair average : shfl_xor 4
// ---------------------------------------------------------------------------
struct EdgeW { float4 wv[4]; };  // 8 x {W1_energy, W2} pairs for this sub

__device__ __forceinline__ float edge_score(uint4 v, float ef, const EdgeW& W, float b2v) {
    const unsigned FULL = 0xffffffffu;
    unsigned px = __shfl_xor_sync(FULL, v.x, 2);
    unsigned py = __shfl_xor_sync(FULL, v.y, 2);
    unsigned pz = __shfl_xor_sync(FULL, v.z, 2);
    unsigned pw = __shfl_xor_sync(FULL, v.w, 2);

    // Endpoint sums in half2, then convert once.
    float2 f0 = __half22float2(__hadd2(u2h(v.x), u2h(px)));
    float2 f1 = __half22float2(__hadd2(u2h(v.y), u2h(py)));
    float2 f2 = __half22float2(__hadd2(u2h(v.z), u2h(pz)));
    float2 f3 = __half22float2(__hadd2(u2h(v.w), u2h(pw)));

    float lg;
    {
        float4 wv = W.wv[0];
        float h0 = fmaxf(fmaf(ef, wv.x, f0.x), 0.0f);
        float h1 = fmaxf(fmaf(ef, wv.z, f0.y), 0.0f);
        lg = h0 * wv.y;
        lg = fmaf(h1, wv.w, lg);
    }
    {
        float4 wv = W.wv[1];
        float h0 = fmaxf(fmaf(ef, wv.x, f1.x), 0.0f);
        float h1 = fmaxf(fmaf(ef, wv.z, f1.y), 0.0f);
        lg = fmaf(h0, wv.y, lg);
        lg = fmaf(h1, wv.w, lg);
    }
    {
        float4 wv = W.wv[2];
        float h0 = fmaxf(fmaf(ef, wv.x, f2.x), 0.0f);
        float h1 = fmaxf(fmaf(ef, wv.z, f2.y), 0.0f);
        lg = fmaf(h0, wv.y, lg);
        lg = fmaf(h1, wv.w, lg);
    }
    {
        float4 wv = W.wv[3];
        float h0 = fmaxf(fmaf(ef, wv.x, f3.x), 0.0f);
        float h1 = fmaxf(fmaf(ef, wv.z, f3.y), 0.0f);
        lg = fmaf(h0, wv.y, lg);
        lg = fmaf(h1, wv.w, lg);
    }

    lg += __shfl_xor_sync(FULL, lg, 1);   // combine the two row halves
    lg += b2v;
    return 1.0f / (1.0f + __expf(-lg));
}

__global__ void edge_kernel(const float* __restrict__ be,
                            const void* __restrict__ ei_raw,
                            const float* __restrict__ W1,
                            const float* __restrict__ W2,
                            const float* __restrict__ We,
                            const float* __restrict__ bE,
                            const float* __restrict__ b2,
                            float* __restrict__ out,
                            int E, int H) {
    __shared__ __align__(16) float2 swp[16];  // {W1[k][32], W2[k]}
    __shared__ float sWe, sbe0, sb2;
    __shared__ int sidx32;

    int tid = threadIdx.x;
    if (tid < 16) {
        swp[tid] = make_float2(__ldg(W1 + tid * 33 + 32), __ldg(W2 + tid));
    } else if (tid == 16) sWe = __ldg(We);
    else if (tid == 17) sbe0 = __ldg(bE);
    else if (tid == 18) sb2 = __ldg(b2);
    else if (tid == 19) sidx32 = g_idx32;
    __syncthreads();

    int gtid = blockIdx.x * blockDim.x + tid;
    int w = gtid >> 5;
    int l = gtid & 31;
    int base0 = w * 16;
    if (base0 >= H) return;  // warp-uniform

    int sub = l & 1;
    int dq = l >> 3;
    int eselH = ((l >> 2) & 1) ? H : 0;
    int epE = ((l >> 1) & 1) ? E : 0;

    EdgeW W;
    {
        const float4* wp = reinterpret_cast<const float4*>(swp) + sub * 4;
#pragma unroll
        for (int t = 0; t < 4; t++) W.wv[t] = wp[t];
    }
    float Wev = sWe, be0v = sbe0, b2v = sb2;
    int idx32 = sidx32;
    const unsigned FULL = 0xffffffffu;

    int o0 = base0 + dq;
    int oArr[4], eArr[4];
#pragma unroll
    for (int g = 0; g < 4; g++) {
        int oR = o0 + 4 * g;
        oArr[g] = oR;
        eArr[g] = min(oR, H - 1) + eselH;
    }

    int r[4];
    if (idx32) {
        const int* p = reinterpret_cast<const int*>(ei_raw);
#pragma unroll
        for (int g = 0; g < 4; g++) r[g] = __ldg(p + eArr[g] + epE);
    } else {
        const long long* p = reinterpret_cast<const long long*>(ei_raw);
#pragma unroll
        for (int g = 0; g < 4; g++) r[g] = (int)__ldg(p + eArr[g] + epE);
    }

    const uint4* tab = reinterpret_cast<const uint4*>(g_projh);
    uint4 v[4];
#pragma unroll
    for (int g = 0; g < 4; g++) v[g] = __ldg(tab + (size_t)r[g] * 2 + sub);

    float bev[4];
#pragma unroll
    for (int g = 0; g < 4; g++) bev[g] = __ldg(be + eArr[g]);

#pragma unroll
    for (int g = 0; g < 4; g++) {
        float ef = fmaf(bev[g], Wev, be0v);
        float sc = edge_score(v[g], ef, W, b2v);
        float res = 0.5f * (sc + __shfl_xor_sync(FULL, sc, 4));
        if ((l & 7) == 0 && oArr[g] < H) out[oArr[g]] = res;
    }
}

// ---------------------------------------------------------------------------

extern "C" void kernel_launch(void* const* d_in, const int* in_sizes, int n_in,
                              void* d_out, int out_size) {
    const float* atoms = (const float*)d_in[0];
    const float* be    = (const float*)d_in[1];
    const float* We    = (const float*)d_in[2];
    const float* bE    = (const float*)d_in[3];
    const float* W1    = (const float*)d_in[4];
    const float* b1    = (const float*)d_in[5];
    const float* W2    = (const float*)d_in[6];
    const float* b2    = (const float*)d_in[7];
    const void*  ei    = d_in[8];
    float* out = (float*)d_out;

    int n = in_sizes[0] / 32;  // atoms
    int E = in_sizes[1];       // edges
    int H = out_size;          // E/2

    int pblocks = (n + 511) / 512;  // 2 atoms per thread
    proj_kernel<<<pblocks, 256>>>(atoms, W1, b1, (const unsigned int*)ei, n);

    long long warps = ((long long)H + 15) / 16;  // 16 outputs per warp
    long long threads = warps * 32;
    int blocks = (int)((threads + 255) / 256);
    edge_kernel<<<blocks, 256>>>(be, ei, W1, W2, We, bE, b2, out, E, H);
}

// round 10
// speedup vs baseline: 2.3341x; 1.0813x over previous
#include <cuda_runtime.h>
#include <cuda_fp16.h>

// ---------------------------------------------------------------------------
// ReactionCenterPredictor
//   inputs: 0 atoms[N,32] f32 | 1 bond_energies[E,1] f32 | 2 W_e[1,1] | 3 b_e[1]
//           4 W1[16,33] | 5 b1[16] | 6 W2[1,16] | 7 b2[1] | 8 edge_index[2,E] i64/i32
//   output: [E/2] f32
//
// v5: proj does 4 atoms/thread (LDS crossbar was the bottleneck — each weight
//     LDS.128 now feeds 4 atoms); edge does 32 outputs/warp with 8 front-
//     batched gather chains and a boundary-free fast path.
// ---------------------------------------------------------------------------

#define MAX_N 1000000

__device__ __align__(16) __half g_projh[MAX_N * 16];  // 32 MB fp16 projection table
__device__ int g_idx32;                               // 1 if edge_index is int32

// ---- packed f32x2 helpers (sm_100a) ---------------------------------------
__device__ __forceinline__ unsigned long long pack2(float x, float y) {
    unsigned long long r;
    asm("mov.b64 %0, {%1, %2};" : "=l"(r) : "f"(x), "f"(y));
    return r;
}
__device__ __forceinline__ void unpack2(unsigned long long v, float& x, float& y) {
    asm("mov.b64 {%0, %1}, %2;" : "=f"(x), "=f"(y) : "l"(v));
}
__device__ __forceinline__ unsigned long long ffma2(unsigned long long a,
                                                    unsigned long long b,
                                                    unsigned long long c) {
    unsigned long long d;
    asm("fma.rn.f32x2 %0, %1, %2, %3;" : "=l"(d) : "l"(a), "l"(b), "l"(c));
    return d;
}
__device__ __forceinline__ __half2 u2h(unsigned u) {
    return *reinterpret_cast<__half2*>(&u);
}

// ---------------------------------------------------------------------------
// K1: per-atom 32->16 projection, b1/2 folded. 4 atoms per thread
// (i, i+256, i+512, i+768) share every weight LDS.128.
// Block 0 also sniffs the edge_index dtype.
// ---------------------------------------------------------------------------
__global__ __launch_bounds__(256) void proj_kernel(
        const float* __restrict__ atoms,
        const float* __restrict__ W1,   // [16,33]
        const float* __restrict__ b1,   // [16]
        const unsigned int* __restrict__ ei_u32,
        int n) {
    __shared__ __align__(16) float sW[32 * 16];  // [j][k] transposed (j<32 only)
    __shared__ float sb1[16];

    int tid = threadIdx.x;

    if (blockIdx.x == 0 && tid == 0) {
        unsigned int acc = 0;
#pragma unroll
        for (int i = 1; i < 128; i += 2) acc |= __ldg(ei_u32 + i);
        g_idx32 = (acc != 0) ? 1 : 0;
    }

    for (int idx = tid; idx < 32 * 16; idx += blockDim.x) {
        int j = idx >> 4, k = idx & 15;
        sW[idx] = __ldg(W1 + k * 33 + j);
    }
    if (tid < 16) sb1[tid] = __ldg(b1 + tid);
    __syncthreads();

    int i0 = blockIdx.x * 1024 + tid;
    if (i0 >= n) return;
    bool va1 = (i0 + 256 < n), va2 = (i0 + 512 < n), va3 = (i0 + 768 < n);

    const float4* __restrict__ ap = reinterpret_cast<const float4*>(atoms) + (size_t)i0 * 8;

    unsigned long long acc[4][8];
#pragma unroll
    for (int c = 0; c < 8; c++) {
        unsigned long long b = pack2(0.5f * sb1[2 * c], 0.5f * sb1[2 * c + 1]);
        acc[0][c] = b; acc[1][c] = b; acc[2][c] = b; acc[3][c] = b;
    }

#pragma unroll
    for (int jc = 0; jc < 8; jc++) {
        float4 A[4];
        A[0] = __ldg(ap + jc);
        A[1] = va1 ? __ldg(ap + 2048 + jc) : make_float4(0.f, 0.f, 0.f, 0.f);
        A[2] = va2 ? __ldg(ap + 4096 + jc) : make_float4(0.f, 0.f, 0.f, 0.f);
        A[3] = va3 ? __ldg(ap + 6144 + jc) : make_float4(0.f, 0.f, 0.f, 0.f);
        float av[4][4];
#pragma unroll
        for (int a = 0; a < 4; a++) {
            av[a][0] = A[a].x; av[a][1] = A[a].y; av[a][2] = A[a].z; av[a][3] = A[a].w;
        }
#pragma unroll
        for (int jj = 0; jj < 4; jj++) {
            int j = 4 * jc + jj;
            unsigned long long aj[4];
#pragma unroll
            for (int a = 0; a < 4; a++) aj[a] = pack2(av[a][jj], av[a][jj]);
            const ulonglong2* wr = reinterpret_cast<const ulonglong2*>(&sW[j * 16]);
#pragma unroll
            for (int c = 0; c < 4; c++) {
                ulonglong2 w = wr[c];   // 4 weights (k = 4c .. 4c+3)
#pragma unroll
                for (int a = 0; a < 4; a++) {
                    acc[a][2 * c + 0] = ffma2(aj[a], w.x, acc[a][2 * c + 0]);
                    acc[a][2 * c + 1] = ffma2(aj[a], w.y, acc[a][2 * c + 1]);
                }
            }
        }
    }

    // Pack fp32 accumulators -> fp16 halves -> 16B stores per atom.
    bool val[4] = {true, va1, va2, va3};
#pragma unroll
    for (int a = 0; a < 4; a++) {
        if (!val[a]) break;
        float x, y;
        unsigned u[8];
#pragma unroll
        for (int c = 0; c < 8; c++) {
            unpack2(acc[a][c], x, y);
            __half2 h = __floats2half2_rn(x, y);
            u[c] = *reinterpret_cast<unsigned*>(&h);
        }
        uint4* dst = reinterpret_cast<uint4*>(g_projh) + ((size_t)i0 + 256 * a) * 2;
        dst[0] = make_uint4(u[0], u[1], u[2], u[3]);
        dst[1] = make_uint4(u[4], u[5], u[6], u[7]);
    }
}

// ---------------------------------------------------------------------------
// K2: 32 outputs per warp = 8 groups of 4. Lane l: sub=l&1 (row half),
// endpoint=(l>>1)&1, edgesel=(l>>2)&1, dq=l>>3 (output slot within group).
// Group g covers output base0 + 4*g + dq. All 8 index loads, 8 gathers and
// 8 energy loads are front-batched before any dependent math.
//   endpoint sum : shfl_xor 2  (HADD2 in half2)
//   dot halves   : shfl_xor 1
//   pair average : shfl_xor 4
// ---------------------------------------------------------------------------
struct EdgeW { float4 wv[4]; };  // 8 x {W1_energy, W2} pairs for this sub

__device__ __forceinline__ float edge_score(uint4 v, float ef, const EdgeW& W, float b2v) {
    const unsigned FULL = 0xffffffffu;
    unsigned px = __shfl_xor_sync(FULL, v.x, 2);
    unsigned py = __shfl_xor_sync(FULL, v.y, 2);
    unsigned pz = __shfl_xor_sync(FULL, v.z, 2);
    unsigned pw = __shfl_xor_sync(FULL, v.w, 2);

    float2 f0 = __half22float2(__hadd2(u2h(v.x), u2h(px)));
    float2 f1 = __half22float2(__hadd2(u2h(v.y), u2h(py)));
    float2 f2 = __half22float2(__hadd2(u2h(v.z), u2h(pz)));
    float2 f3 = __half22float2(__hadd2(u2h(v.w), u2h(pw)));

    float lg;
    {
        float4 wv = W.wv[0];
        float h0 = fmaxf(fmaf(ef, wv.x, f0.x), 0.0f);
        float h1 = fmaxf(fmaf(ef, wv.z, f0.y), 0.0f);
        lg = h0 * wv.y;
        lg = fmaf(h1, wv.w, lg);
    }
    {
        float4 wv = W.wv[1];
        float h0 = fmaxf(fmaf(ef, wv.x, f1.x), 0.0f);
        float h1 = fmaxf(fmaf(ef, wv.z, f1.y), 0.0f);
        lg = fmaf(h0, wv.y, lg);
        lg = fmaf(h1, wv.w, lg);
    }
    {
        float4 wv = W.wv[2];
        float h0 = fmaxf(fmaf(ef, wv.x, f2.x), 0.0f);
        float h1 = fmaxf(fmaf(ef, wv.z, f2.y), 0.0f);
        lg = fmaf(h0, wv.y, lg);
        lg = fmaf(h1, wv.w, lg);
    }
    {
        float4 wv = W.wv[3];
        float h0 = fmaxf(fmaf(ef, wv.x, f3.x), 0.0f);
        float h1 = fmaxf(fmaf(ef, wv.z, f3.y), 0.0f);
        lg = fmaf(h0, wv.y, lg);
        lg = fmaf(h1, wv.w, lg);
    }

    lg += __shfl_xor_sync(FULL, lg, 1);   // combine the two row halves
    lg += b2v;
    return 1.0f / (1.0f + __expf(-lg));
}

__global__ __launch_bounds__(256) void edge_kernel(
        const float* __restrict__ be,
        const void* __restrict__ ei_raw,
        const float* __restrict__ W1,
        const float* __restrict__ W2,
        const float* __restrict__ We,
        const float* __restrict__ bE,
        const float* __restrict__ b2,
        float* __restrict__ out,
        int E, int H) {
    __shared__ __align__(16) float2 swp[16];  // {W1[k][32], W2[k]}
    __shared__ float sWe, sbe0, sb2;
    __shared__ int sidx32;

    int tid = threadIdx.x;
    if (tid < 16) {
        swp[tid] = make_float2(__ldg(W1 + tid * 33 + 32), __ldg(W2 + tid));
    } else if (tid == 16) sWe = __ldg(We);
    else if (tid == 17) sbe0 = __ldg(bE);
    else if (tid == 18) sb2 = __ldg(b2);
    else if (tid == 19) sidx32 = g_idx32;
    __syncthreads();

    int gtid = blockIdx.x * blockDim.x + tid;
    int w = gtid >> 5;
    int l = gtid & 31;
    int base0 = w * 32;
    if (base0 >= H) return;  // warp-uniform

    int sub = l & 1;
    int dq = l >> 3;
    int eselH = ((l >> 2) & 1) ? H : 0;
    int epE = ((l >> 1) & 1) ? E : 0;

    EdgeW W;
    {
        const float4* wp = reinterpret_cast<const float4*>(swp) + sub * 4;
#pragma unroll
        for (int t = 0; t < 4; t++) W.wv[t] = wp[t];
    }
    float Wev = sWe, be0v = sbe0, b2v = sb2;
    int idx32 = sidx32;
    const unsigned FULL = 0xffffffffu;

    int o0 = base0 + dq;
    bool full = (base0 + 32 <= H);  // warp-uniform fast path
    int eA[8];
    if (full) {
#pragma unroll
        for (int g = 0; g < 8; g++) eA[g] = o0 + 4 * g + eselH;
    } else {
#pragma unroll
        for (int g = 0; g < 8; g++) eA[g] = min(o0 + 4 * g, H - 1) + eselH;
    }

    int r[8];
    if (idx32) {
        const int* p = reinterpret_cast<const int*>(ei_raw);
#pragma unroll
        for (int g = 0; g < 8; g++) r[g] = __ldg(p + eA[g] + epE);
    } else {
        const long long* p = reinterpret_cast<const long long*>(ei_raw);
#pragma unroll
        for (int g = 0; g < 8; g++) r[g] = (int)__ldg(p + eA[g] + epE);
    }

    const uint4* tab = reinterpret_cast<const uint4*>(g_projh);
    uint4 v[8];
#pragma unroll
    for (int g = 0; g < 8; g++) v[g] = __ldg(tab + (size_t)r[g] * 2 + sub);

    float bev[8];
#pragma unroll
    for (int g = 0; g < 8; g++) bev[g] = __ldg(be + eA[g]);

#pragma unroll
    for (int g = 0; g < 8; g++) {
        float ef = fmaf(bev[g], Wev, be0v);
        float sc = edge_score(v[g], ef, W, b2v);
        float res = 0.5f * (sc + __shfl_xor_sync(FULL, sc, 4));
        int oR = o0 + 4 * g;
        if ((l & 7) == 0 && (full || oR < H)) out[oR] = res;
    }
}

// ---------------------------------------------------------------------------

extern "C" void kernel_launch(void* const* d_in, const int* in_sizes, int n_in,
                              void* d_out, int out_size) {
    const float* atoms = (const float*)d_in[0];
    const float* be    = (const float*)d_in[1];
    const float* We    = (const float*)d_in[2];
    const float* bE    = (const float*)d_in[3];
    const float* W1    = (const float*)d_in[4];
    const float* b1    = (const float*)d_in[5];
    const float* W2    = (const float*)d_in[6];
    const float* b2    = (const float*)d_in[7];
    const void*  ei    = d_in[8];
    float* out = (float*)d_out;

    int n = in_sizes[0] / 32;  // atoms
    int E = in_sizes[1];       // edges
    int H = out_size;          // E/2

    int pblocks = (n + 1023) / 1024;  // 4 atoms per thread
    proj_kernel<<<pblocks, 256>>>(atoms, W1, b1, (const unsigned int*)ei, n);

    long long warps = ((long long)H + 31) / 32;  // 32 outputs per warp
    long long threads = warps * 32;
    int blocks = (int)((threads + 255) / 256);
    edge_kernel<<<blocks, 256>>>(be, ei, W1, W2, We, bE, b2, out, E, H);
}

// round 11
// speedup vs baseline: 3.1635x; 1.3553x over previous
#include <cuda_runtime.h>
#include <cuda_fp16.h>
#include <mma.h>

// ---------------------------------------------------------------------------
// ReactionCenterPredictor
//   inputs: 0 atoms[N,32] f32 | 1 bond_energies[E,1] f32 | 2 W_e[1,1] | 3 b_e[1]
//           4 W1[16,33] | 5 b1[16] | 6 W2[1,16] | 7 b2[1] | 8 edge_index[2,E] i64/i32
//   output: [E/2] f32
//
// v6: proj is a tf32 wmma GEMM (tensor pipe; scalar FMA/LDS issue deleted,
//     kernel becomes a 160MB stream). Edge: 4 lanes/output, each lane loads
//     both endpoint half-rows itself -> endpoint shuffles eliminated.
// ---------------------------------------------------------------------------

#define MAX_N 1000000

__device__ __align__(16) __half g_projh[MAX_N * 16];  // 32 MB fp16 projection table
__device__ int g_idx32;                               // 1 if edge_index is int32

__device__ __forceinline__ __half2 u2h(unsigned u) {
    return *reinterpret_cast<__half2*>(&u);
}

using namespace nvcuda;

// ---------------------------------------------------------------------------
// K1: [n,32] @ [32,16] via wmma tf32 m16n16k8. Each warp: 4 tiles of 16 atoms.
// Accum staged via shared (ld=24 floats, 16B-aligned rows), bias added at
// pack time, output packed to fp16 (2 x STG.128 per atom, coalesced).
// Block 0 also sniffs index dtype and handles the <16-atom remainder.
// ---------------------------------------------------------------------------
#define PROJ_TPW 4           // tiles per warp
#define PROJ_TPB 32          // tiles per block (8 warps)
#define SC_LD 24             // floats per row in staging buffer

__global__ __launch_bounds__(256) void proj_kernel(
        const float* __restrict__ atoms,
        const float* __restrict__ W1,   // [16,33]
        const float* __restrict__ b1,   // [16]
        const unsigned int* __restrict__ ei_u32,
        int n) {
    __shared__ __align__(16) float sB[32 * 16];          // [j][k] W1 transposed
    __shared__ __align__(16) float sC[8][16 * SC_LD];    // per-warp accum staging
    __shared__ float sb1[16];

    int tid = threadIdx.x;
    int wid = tid >> 5;
    int l = tid & 31;

    if (blockIdx.x == 0 && tid == 0) {
        unsigned int acc = 0;
#pragma unroll
        for (int i = 1; i < 128; i += 2) acc |= __ldg(ei_u32 + i);
        g_idx32 = (acc != 0) ? 1 : 0;
    }

    for (int idx = tid; idx < 32 * 16; idx += 256) {
        int j = idx >> 4, k = idx & 15;
        sB[idx] = __ldg(W1 + k * 33 + j);
    }
    if (tid < 16) sb1[tid] = __ldg(b1 + tid);
    __syncthreads();

    // B fragments (shared across all tiles of this warp).
    wmma::fragment<wmma::matrix_b, 16, 16, 8, wmma::precision::tf32, wmma::row_major> bF[4];
#pragma unroll
    for (int s = 0; s < 4; s++) {
        wmma::load_matrix_sync(bF[s], sB + s * 8 * 16, 16);
#pragma unroll
        for (int t = 0; t < bF[s].num_elements; t++)
            bF[s].x[t] = wmma::__float_to_tf32(bF[s].x[t]);
    }

    // Per-lane pack constants: atom_local = l>>1, half = l&1, k = half*8 + i.
    int atom_local = l >> 1;
    int half = l & 1;
    float hb[8];
#pragma unroll
    for (int i = 0; i < 8; i++) hb[i] = 0.5f * sb1[half * 8 + i];

    int tiles = n >> 4;
    int tile0 = blockIdx.x * PROJ_TPB + wid * PROJ_TPW;
    float* sCw = sC[wid];

    for (int t = 0; t < PROJ_TPW; t++) {
        int tile = tile0 + t;
        if (tile >= tiles) break;
        const float* aPtr = atoms + (size_t)tile * 512;  // 16 atoms x 32 floats

        wmma::fragment<wmma::accumulator, 16, 16, 8, float> cF;
        wmma::fill_fragment(cF, 0.0f);
#pragma unroll
        for (int s = 0; s < 4; s++) {
            wmma::fragment<wmma::matrix_a, 16, 16, 8, wmma::precision::tf32, wmma::row_major> aF;
            wmma::load_matrix_sync(aF, aPtr + s * 8, 32);
#pragma unroll
            for (int q = 0; q < aF.num_elements; q++)
                aF.x[q] = wmma::__float_to_tf32(aF.x[q]);
            wmma::mma_sync(cF, aF, bF[s], cF);
        }
        wmma::store_matrix_sync(sCw, cF, SC_LD, wmma::mem_row_major);
        __syncwarp();

        // Pack: lane -> one uint4 (8 k's) of one atom row.
        const float4* src = reinterpret_cast<const float4*>(sCw + atom_local * SC_LD + half * 8);
        float4 p0 = src[0], p1 = src[1];
        __half2 h0 = __floats2half2_rn(p0.x + hb[0], p0.y + hb[1]);
        __half2 h1 = __floats2half2_rn(p0.z + hb[2], p0.w + hb[3]);
        __half2 h2 = __floats2half2_rn(p1.x + hb[4], p1.y + hb[5]);
        __half2 h3 = __floats2half2_rn(p1.z + hb[6], p1.w + hb[7]);
        uint4 o;
        o.x = *reinterpret_cast<unsigned*>(&h0);
        o.y = *reinterpret_cast<unsigned*>(&h1);
        o.z = *reinterpret_cast<unsigned*>(&h2);
        o.w = *reinterpret_cast<unsigned*>(&h3);
        reinterpret_cast<uint4*>(g_projh)[((size_t)tile * 16 + atom_local) * 2 + half] = o;
        __syncwarp();
    }

    // Remainder atoms (n % 16), scalar path in block 0.
    int rem = n & 15;
    if (blockIdx.x == 0 && tid < rem) {
        int atom = tiles * 16 + tid;
        const float* ar = atoms + (size_t)atom * 32;
        unsigned u[8];
#pragma unroll
        for (int c = 0; c < 8; c++) {
            float acc0 = 0.5f * sb1[2 * c], acc1 = 0.5f * sb1[2 * c + 1];
            for (int j = 0; j < 32; j++) {
                float aj = __ldg(ar + j);
                acc0 = fmaf(aj, sB[j * 16 + 2 * c], acc0);
                acc1 = fmaf(aj, sB[j * 16 + 2 * c + 1], acc1);
            }
            __half2 h = __floats2half2_rn(acc0, acc1);
            u[c] = *reinterpret_cast<unsigned*>(&h);
        }
        uint4* dst = reinterpret_cast<uint4*>(g_projh) + (size_t)atom * 2;
        dst[0] = make_uint4(u[0], u[1], u[2], u[3]);
        dst[1] = make_uint4(u[4], u[5], u[6], u[7]);
    }
}

// ---------------------------------------------------------------------------
// K2: 4 lanes per output, each lane loads BOTH endpoint half-rows (no
// endpoint shuffles). Lane l: sub=l&1 (row half), esel=(l>>1)&1 (edge of
// pair), slot=l>>2 (0..7 -> 8 outputs per iteration). 4 iterations = 32
// outputs/warp, loads front-batched across iterations.
//   dot-combine : shfl_xor 1   (other sub)
//   pair average: shfl_xor 2   (other edge)
// ---------------------------------------------------------------------------
struct EdgeW { float4 wv[4]; };  // 8 x {W1_energy, W2} pairs for this sub

__global__ __launch_bounds__(256) void edge_kernel(
        const float* __restrict__ be,
        const void* __restrict__ ei_raw,
        const float* __restrict__ W1,
        const float* __restrict__ W2,
        const float* __restrict__ We,
        const float* __restrict__ bE,
        const float* __restrict__ b2,
        float* __restrict__ out,
        int E, int H) {
    __shared__ __align__(16) float2 swp[16];  // {W1[k][32], W2[k]}
    __shared__ float sWe, sbe0, sb2;
    __shared__ int sidx32;

    int tid = threadIdx.x;
    if (tid < 16) {
        swp[tid] = make_float2(__ldg(W1 + tid * 33 + 32), __ldg(W2 + tid));
    } else if (tid == 16) sWe = __ldg(We);
    else if (tid == 17) sbe0 = __ldg(bE);
    else if (tid == 18) sb2 = __ldg(b2);
    else if (tid == 19) sidx32 = g_idx32;
    __syncthreads();

    int gtid = blockIdx.x * blockDim.x + tid;
    int w = gtid >> 5;
    int l = gtid & 31;
    int base0 = w * 32;
    if (base0 >= H) return;  // warp-uniform

    int sub = l & 1;
    int eselH = ((l >> 1) & 1) ? H : 0;
    int slot = l >> 2;

    EdgeW W;
    {
        const float4* wp = reinterpret_cast<const float4*>(swp) + sub * 4;
#pragma unroll
        for (int t = 0; t < 4; t++) W.wv[t] = wp[t];
    }
    float Wev = sWe, be0v = sbe0, b2v = sb2;
    int idx32 = sidx32;
    const unsigned FULL = 0xffffffffu;

    bool full = (base0 + 32 <= H);  // warp-uniform fast path
    int eA[4];
    if (full) {
#pragma unroll
        for (int it = 0; it < 4; it++) eA[it] = base0 + it * 8 + slot + eselH;
    } else {
#pragma unroll
        for (int it = 0; it < 4; it++) eA[it] = min(base0 + it * 8 + slot, H - 1) + eselH;
    }

    // Front-batch: all index loads, then all gathers, then all energies.
    int rs[4], rd[4];
    if (idx32) {
        const int* p = reinterpret_cast<const int*>(ei_raw);
#pragma unroll
        for (int it = 0; it < 4; it++) { rs[it] = __ldg(p + eA[it]); rd[it] = __ldg(p + eA[it] + E); }
    } else {
        const long long* p = reinterpret_cast<const long long*>(ei_raw);
#pragma unroll
        for (int it = 0; it < 4; it++) { rs[it] = (int)__ldg(p + eA[it]); rd[it] = (int)__ldg(p + eA[it] + E); }
    }

    const uint4* tab = reinterpret_cast<const uint4*>(g_projh);
    uint4 vs[4], vd[4];
#pragma unroll
    for (int it = 0; it < 4; it++) vs[it] = __ldg(tab + (size_t)rs[it] * 2 + sub);
#pragma unroll
    for (int it = 0; it < 4; it++) vd[it] = __ldg(tab + (size_t)rd[it] * 2 + sub);

    float bev[4];
#pragma unroll
    for (int it = 0; it < 4; it++) bev[it] = __ldg(be + eA[it]);

#pragma unroll
    for (int it = 0; it < 4; it++) {
        // Endpoint sum in half2 — no shuffles.
        float2 f0 = __half22float2(__hadd2(u2h(vs[it].x), u2h(vd[it].x)));
        float2 f1 = __half22float2(__hadd2(u2h(vs[it].y), u2h(vd[it].y)));
        float2 f2 = __half22float2(__hadd2(u2h(vs[it].z), u2h(vd[it].z)));
        float2 f3 = __half22float2(__hadd2(u2h(vs[it].w), u2h(vd[it].w)));

        float ef = fmaf(bev[it], Wev, be0v);

        float lg;
        {
            float4 wv = W.wv[0];
            float h0 = fmaxf(fmaf(ef, wv.x, f0.x), 0.0f);
            float h1 = fmaxf(fmaf(ef, wv.z, f0.y), 0.0f);
            lg = h0 * wv.y;
            lg = fmaf(h1, wv.w, lg);
        }
        {
            float4 wv = W.wv[1];
            float h0 = fmaxf(fmaf(ef, wv.x, f1.x), 0.0f);
            float h1 = fmaxf(fmaf(ef, wv.z, f1.y), 0.0f);
            lg = fmaf(h0, wv.y, lg);
            lg = fmaf(h1, wv.w, lg);
        }
        {
            float4 wv = W.wv[2];
            float h0 = fmaxf(fmaf(ef, wv.x, f2.x), 0.0f);
            float h1 = fmaxf(fmaf(ef, wv.z, f2.y), 0.0f);
            lg = fmaf(h0, wv.y, lg);
            lg = fmaf(h1, wv.w, lg);
        }
        {
            float4 wv = W.wv[3];
            float h0 = fmaxf(fmaf(ef, wv.x, f3.x), 0.0f);
            float h1 = fmaxf(fmaf(ef, wv.z, f3.y), 0.0f);
            lg = fmaf(h0, wv.y, lg);
            lg = fmaf(h1, wv.w, lg);
        }

        lg += __shfl_xor_sync(FULL, lg, 1);   // other sub (row half)
        lg += b2v;
        float sc = 1.0f / (1.0f + __expf(-lg));

        float res = 0.5f * (sc + __shfl_xor_sync(FULL, sc, 2));  // other edge of pair

        int oR = base0 + it * 8 + slot;
        if ((l & 3) == 0 && (full || oR < H)) out[oR] = res;
    }
}

// ---------------------------------------------------------------------------

extern "C" void kernel_launch(void* const* d_in, const int* in_sizes, int n_in,
                              void* d_out, int out_size) {
    const float* atoms = (const float*)d_in[0];
    const float* be    = (const float*)d_in[1];
    const float* We    = (const float*)d_in[2];
    const float* bE    = (const float*)d_in[3];
    const float* W1    = (const float*)d_in[4];
    const float* b1    = (const float*)d_in[5];
    const float* W2    = (const float*)d_in[6];
    const float* b2    = (const float*)d_in[7];
    const void*  ei    = d_in[8];
    float* out = (float*)d_out;

    int n = in_sizes[0] / 32;  // atoms
    int E = in_sizes[1];       // edges
    int H = out_size;          // E/2

    int tiles = n >> 4;
    int pblocks = (tiles + PROJ_TPB - 1) / PROJ_TPB;
    if (pblocks < 1) pblocks = 1;
    proj_kernel<<<pblocks, 256>>>(atoms, W1, b1, (const unsigned int*)ei, n);

    long long warps = ((long long)H + 31) / 32;  // 32 outputs per warp
    long long threads = warps * 32;
    int blocks = (int)((threads + 255) / 256);
    edge_kernel<<<blocks, 256>>>(be, ei, W1, W2, We, bE, b2, out, E, H);
}

// round 12
// speedup vs baseline: 3.6334x; 1.1486x over previous
#include <cuda_runtime.h>
#include <cuda_fp16.h>
#include <mma.h>

// ---------------------------------------------------------------------------
// ReactionCenterPredictor
//   inputs: 0 atoms[N,32] f32 | 1 bond_energies[E,1] f32 | 2 W_e[1,1] | 3 b_e[1]
//           4 W1[16,33] | 5 b1[16] | 6 W2[1,16] | 7 b2[1] | 8 edge_index[2,E] i64/i32
//   output: [E/2] f32
//
// v7: proj stages A-tiles through shared with coalesced float4 loads +
//     register prefetch (v6's scattered wmma global fragment loads were the
//     proj bottleneck). Edge unchanged (at gather-replay floor).
// ---------------------------------------------------------------------------

#define MAX_N 1000000

__device__ __align__(16) __half g_projh[MAX_N * 16];  // 32 MB fp16 projection table
__device__ int g_idx32;                               // 1 if edge_index is int32

__device__ __forceinline__ __half2 u2h(unsigned u) {
    return *reinterpret_cast<__half2*>(&u);
}

using namespace nvcuda;

// ---------------------------------------------------------------------------
// K1: [n,32] @ [32,16] via wmma tf32 m16n16k8, 8 tiles/warp.
// A staged: coalesced LDG.128 -> regs -> STS (ld=36 pad) -> load_matrix_sync,
// with next tile prefetched into regs during current tile's mma/pack.
// ---------------------------------------------------------------------------
#define PROJ_TPW 8           // tiles per warp
#define PROJ_TPB 64          // tiles per block (8 warps)
#define A_LD 36              // A staging row stride (floats)
#define SC_LD 24             // C staging row stride (floats)

__global__ __launch_bounds__(256) void proj_kernel(
        const float* __restrict__ atoms,
        const float* __restrict__ W1,   // [16,33]
        const float* __restrict__ b1,   // [16]
        const unsigned int* __restrict__ ei_u32,
        int n) {
    __shared__ __align__(16) float sB[32 * 16];          // [j][k] W1 transposed
    __shared__ __align__(16) float sA[8][16 * A_LD];     // per-warp A staging
    __shared__ __align__(16) float sC[8][16 * SC_LD];    // per-warp accum staging
    __shared__ float sb1[16];

    int tid = threadIdx.x;
    int wid = tid >> 5;
    int l = tid & 31;

    if (blockIdx.x == 0 && tid == 0) {
        unsigned int acc = 0;
#pragma unroll
        for (int i = 1; i < 128; i += 2) acc |= __ldg(ei_u32 + i);
        g_idx32 = (acc != 0) ? 1 : 0;
    }

    for (int idx = tid; idx < 32 * 16; idx += 256) {
        int j = idx >> 4, k = idx & 15;
        sB[idx] = __ldg(W1 + k * 33 + j);
    }
    if (tid < 16) sb1[tid] = __ldg(b1 + tid);
    __syncthreads();

    // B fragments (shared across all tiles of this warp).
    wmma::fragment<wmma::matrix_b, 16, 16, 8, wmma::precision::tf32, wmma::row_major> bF[4];
#pragma unroll
    for (int s = 0; s < 4; s++) {
        wmma::load_matrix_sync(bF[s], sB + s * 8 * 16, 16);
#pragma unroll
        for (int t = 0; t < bF[s].num_elements; t++)
            bF[s].x[t] = wmma::__float_to_tf32(bF[s].x[t]);
    }

    // Staging lane constants: float4 idx = i*32 + l -> (row, c4).
    int strow[4], stc4[4];
#pragma unroll
    for (int i = 0; i < 4; i++) {
        int idx = i * 32 + l;
        strow[i] = idx >> 3;
        stc4[i] = idx & 7;
    }

    // Pack lane constants: atom_local = l>>1, half = l&1.
    int atom_local = l >> 1;
    int half = l & 1;
    float hb[8];
#pragma unroll
    for (int i = 0; i < 8; i++) hb[i] = 0.5f * sb1[half * 8 + i];

    int tiles = n >> 4;
    int tile0 = blockIdx.x * PROJ_TPB + wid * PROJ_TPW;
    float* sAw = sA[wid];
    float* sCw = sC[wid];

    int nt = tiles - tile0;
    if (nt > PROJ_TPW) nt = PROJ_TPW;

    float4 buf[4];
    if (nt > 0) {
        const float4* ap = reinterpret_cast<const float4*>(atoms) + (size_t)tile0 * 128;
#pragma unroll
        for (int i = 0; i < 4; i++) buf[i] = __ldg(ap + i * 32 + l);
    }

    for (int t = 0; t < nt; t++) {
        // Stage current tile (coalesced regs -> shared, padded rows).
#pragma unroll
        for (int i = 0; i < 4; i++)
            *reinterpret_cast<float4*>(&sAw[strow[i] * A_LD + stc4[i] * 4]) = buf[i];
        __syncwarp();

        // Prefetch next tile while mma/pack of current proceeds.
        if (t + 1 < nt) {
            const float4* ap =
                reinterpret_cast<const float4*>(atoms) + (size_t)(tile0 + t + 1) * 128;
#pragma unroll
            for (int i = 0; i < 4; i++) buf[i] = __ldg(ap + i * 32 + l);
        }

        wmma::fragment<wmma::accumulator, 16, 16, 8, float> cF;
        wmma::fill_fragment(cF, 0.0f);
#pragma unroll
        for (int s = 0; s < 4; s++) {
            wmma::fragment<wmma::matrix_a, 16, 16, 8, wmma::precision::tf32, wmma::row_major> aF;
            wmma::load_matrix_sync(aF, sAw + s * 8, A_LD);
#pragma unroll
            for (int q = 0; q < aF.num_elements; q++)
                aF.x[q] = wmma::__float_to_tf32(aF.x[q]);
            wmma::mma_sync(cF, aF, bF[s], cF);
        }
        wmma::store_matrix_sync(sCw, cF, SC_LD, wmma::mem_row_major);
        __syncwarp();   // sA fully read (load_matrix done) + sC visible

        // Pack: lane -> one uint4 (8 k's) of one atom row.
        const float4* src = reinterpret_cast<const float4*>(sCw + atom_local * SC_LD + half * 8);
        float4 p0 = src[0], p1 = src[1];
        __half2 h0 = __floats2half2_rn(p0.x + hb[0], p0.y + hb[1]);
        __half2 h1 = __floats2half2_rn(p0.z + hb[2], p0.w + hb[3]);
        __half2 h2 = __floats2half2_rn(p1.x + hb[4], p1.y + hb[5]);
        __half2 h3 = __floats2half2_rn(p1.z + hb[6], p1.w + hb[7]);
        uint4 o;
        o.x = *reinterpret_cast<unsigned*>(&h0);
        o.y = *reinterpret_cast<unsigned*>(&h1);
        o.z = *reinterpret_cast<unsigned*>(&h2);
        o.w = *reinterpret_cast<unsigned*>(&h3);
        int tile = tile0 + t;
        reinterpret_cast<uint4*>(g_projh)[((size_t)tile * 16 + atom_local) * 2 + half] = o;
    }

    // Remainder atoms (n % 16), scalar path in block 0.
    int rem = n & 15;
    if (blockIdx.x == 0 && tid < rem) {
        int atom = tiles * 16 + tid;
        const float* ar = atoms + (size_t)atom * 32;
        unsigned u[8];
#pragma unroll
        for (int c = 0; c < 8; c++) {
            float acc0 = 0.5f * sb1[2 * c], acc1 = 0.5f * sb1[2 * c + 1];
            for (int j = 0; j < 32; j++) {
                float aj = __ldg(ar + j);
                acc0 = fmaf(aj, sB[j * 16 + 2 * c], acc0);
                acc1 = fmaf(aj, sB[j * 16 + 2 * c + 1], acc1);
            }
            __half2 h = __floats2half2_rn(acc0, acc1);
            u[c] = *reinterpret_cast<unsigned*>(&h);
        }
        uint4* dst = reinterpret_cast<uint4*>(g_projh) + (size_t)atom * 2;
        dst[0] = make_uint4(u[0], u[1], u[2], u[3]);
        dst[1] = make_uint4(u[4], u[5], u[6], u[7]);
    }
}

// ---------------------------------------------------------------------------
// K2 (unchanged from v6): 4 lanes per output, each lane loads BOTH endpoint
// half-rows (no endpoint shuffles). 32 outputs/warp, loads front-batched.
//   dot-combine : shfl_xor 1   (other sub)
//   pair average: shfl_xor 2   (other edge)
// ---------------------------------------------------------------------------
struct EdgeW { float4 wv[4]; };  // 8 x {W1_energy, W2} pairs for this sub

__global__ __launch_bounds__(256) void edge_kernel(
        const float* __restrict__ be,
        const void* __restrict__ ei_raw,
        const float* __restrict__ W1,
        const float* __restrict__ W2,
        const float* __restrict__ We,
        const float* __restrict__ bE,
        const float* __restrict__ b2,
        float* __restrict__ out,
        int E, int H) {
    __shared__ __align__(16) float2 swp[16];  // {W1[k][32], W2[k]}
    __shared__ float sWe, sbe0, sb2;
    __shared__ int sidx32;

    int tid = threadIdx.x;
    if (tid < 16) {
        swp[tid] = make_float2(__ldg(W1 + tid * 33 + 32), __ldg(W2 + tid));
    } else if (tid == 16) sWe = __ldg(We);
    else if (tid == 17) sbe0 = __ldg(bE);
    else if (tid == 18) sb2 = __ldg(b2);
    else if (tid == 19) sidx32 = g_idx32;
    __syncthreads();

    int gtid = blockIdx.x * blockDim.x + tid;
    int w = gtid >> 5;
    int l = gtid & 31;
    int base0 = w * 32;
    if (base0 >= H) return;  // warp-uniform

    int sub = l & 1;
    int eselH = ((l >> 1) & 1) ? H : 0;
    int slot = l >> 2;

    EdgeW W;
    {
        const float4* wp = reinterpret_cast<const float4*>(swp) + sub * 4;
#pragma unroll
        for (int t = 0; t < 4; t++) W.wv[t] = wp[t];
    }
    float Wev = sWe, be0v = sbe0, b2v = sb2;
    int idx32 = sidx32;
    const unsigned FULL = 0xffffffffu;

    bool full = (base0 + 32 <= H);  // warp-uniform fast path
    int eA[4];
    if (full) {
#pragma unroll
        for (int it = 0; it < 4; it++) eA[it] = base0 + it * 8 + slot + eselH;
    } else {
#pragma unroll
        for (int it = 0; it < 4; it++) eA[it] = min(base0 + it * 8 + slot, H - 1) + eselH;
    }

    // Front-batch: all index loads, then all gathers, then all energies.
    int rs[4], rd[4];
    if (idx32) {
        const int* p = reinterpret_cast<const int*>(ei_raw);
#pragma unroll
        for (int it = 0; it < 4; it++) { rs[it] = __ldg(p + eA[it]); rd[it] = __ldg(p + eA[it] + E); }
    } else {
        const long long* p = reinterpret_cast<const long long*>(ei_raw);
#pragma unroll
        for (int it = 0; it < 4; it++) { rs[it] = (int)__ldg(p + eA[it]); rd[it] = (int)__ldg(p + eA[it] + E); }
    }

    const uint4* tab = reinterpret_cast<const uint4*>(g_projh);
    uint4 vs[4], vd[4];
#pragma unroll
    for (int it = 0; it < 4; it++) vs[it] = __ldg(tab + (size_t)rs[it] * 2 + sub);
#pragma unroll
    for (int it = 0; it < 4; it++) vd[it] = __ldg(tab + (size_t)rd[it] * 2 + sub);

    float bev[4];
#pragma unroll
    for (int it = 0; it < 4; it++) bev[it] = __ldg(be + eA[it]);

#pragma unroll
    for (int it = 0; it < 4; it++) {
        // Endpoint sum in half2 — no shuffles.
        float2 f0 = __half22float2(__hadd2(u2h(vs[it].x), u2h(vd[it].x)));
        float2 f1 = __half22float2(__hadd2(u2h(vs[it].y), u2h(vd[it].y)));
        float2 f2 = __half22float2(__hadd2(u2h(vs[it].z), u2h(vd[it].z)));
        float2 f3 = __half22float2(__hadd2(u2h(vs[it].w), u2h(vd[it].w)));

        float ef = fmaf(bev[it], Wev, be0v);

        float lg;
        {
            float4 wv = W.wv[0];
            float h0 = fmaxf(fmaf(ef, wv.x, f0.x), 0.0f);
            float h1 = fmaxf(fmaf(ef, wv.z, f0.y), 0.0f);
            lg = h0 * wv.y;
            lg = fmaf(h1, wv.w, lg);
        }
        {
            float4 wv = W.wv[1];
            float h0 = fmaxf(fmaf(ef, wv.x, f1.x), 0.0f);
            float h1 = fmaxf(fmaf(ef, wv.z, f1.y), 0.0f);
            lg = fmaf(h0, wv.y, lg);
            lg = fmaf(h1, wv.w, lg);
        }
        {
            float4 wv = W.wv[2];
            float h0 = fmaxf(fmaf(ef, wv.x, f2.x), 0.0f);
            float h1 = fmaxf(fmaf(ef, wv.z, f2.y), 0.0f);
            lg = fmaf(h0, wv.y, lg);
            lg = fmaf(h1, wv.w, lg);
        }
        {
            float4 wv = W.wv[3];
            float h0 = fmaxf(fmaf(ef, wv.x, f3.x), 0.0f);
            float h1 = fmaxf(fmaf(ef, wv.z, f3.y), 0.0f);
            lg = fmaf(h0, wv.y, lg);
            lg = fmaf(h1, wv.w, lg);
        }

        lg += __shfl_xor_sync(FULL, lg, 1);   // other sub (row half)
        lg += b2v;
        float sc = 1.0f / (1.0f + __expf(-lg));

        float res = 0.5f * (sc + __shfl_xor_sync(FULL, sc, 2));  // other edge of pair

        int oR = base0 + it * 8 + slot;
        if ((l & 3) == 0 && (full || oR < H)) out[oR] = res;
    }
}

// ---------------------------------------------------------------------------

extern "C" void kernel_launch(void* const* d_in, const int* in_sizes, int n_in,
                              void* d_out, int out_size) {
    const float* atoms = (const float*)d_in[0];
    const float* be    = (const float*)d_in[1];
    const float* We    = (const float*)d_in[2];
    const float* bE    = (const float*)d_in[3];
    const float* W1    = (const float*)d_in[4];
    const float* b1    = (const float*)d_in[5];
    const float* W2    = (const float*)d_in[6];
    const float* b2    = (const float*)d_in[7];
    const void*  ei    = d_in[8];
    float* out = (float*)d_out;

    int n = in_sizes[0] / 32;  // atoms
    int E = in_sizes[1];       // edges
    int H = out_size;          // E/2

    int tiles = n >> 4;
    int pblocks = (tiles + PROJ_TPB - 1) / PROJ_TPB;
    if (pblocks < 1) pblocks = 1;
    proj_kernel<<<pblocks, 256>>>(atoms, W1, b1, (const unsigned int*)ei, n);

    long long warps = ((long long)H + 31) / 32;  // 32 outputs per warp
    long long threads = warps * 32;
    int blocks = (int)((threads + 255) / 256);
    edge_kernel<<<blocks, 256>>>(be, ei, W1, W2, We, bE, b2, out, E, H);
}